// round 3
// baseline (speedup 1.0000x reference)
#include <cuda_runtime.h>
#include <cuda_bf16.h>

// ---------------- problem constants ----------------
#define NN     200000   // nodes
#define DFEAT  128
#define EE     8192     // events
#define HH     64
#define TE     32
#define EA     32
#define AA     50
#define KMSG   (2*HH + EA + TE)   // 192

// ---------------- scratch (static device globals; allocation is forbidden) --
__device__ float g_h[(size_t)NN * HH];     // node memory   (51.2 MB)
__device__ float g_c[(size_t)NN * HH];     // LSTM cell     (51.2 MB)
__device__ float g_te[EE * TE];            // time encodings (1 MB)
__device__ float g_W2[KMSG * AA];          // fused W_emb @ W_cls
__device__ float g_b2[AA];                 // fused bias

// ---------------- helpers ----------------
using ull = unsigned long long;

__device__ __forceinline__ ull ffma2(ull a, ull b, ull c) {
    ull d;
    asm("fma.rn.f32x2 %0, %1, %2, %3;" : "=l"(d) : "l"(a), "l"(b), "l"(c));
    return d;
}
__device__ __forceinline__ ull f2u(float x, float y) {
    ull v;
    asm("mov.b64 %0, {%1, %2};" : "=l"(v) : "f"(x), "f"(y));
    return v;
}
__device__ __forceinline__ float2 u2f(ull v) {
    float2 r;
    asm("mov.b64 {%0, %1}, %2;" : "=f"(r.x), "=f"(r.y) : "l"(v));
    return r;
}
__device__ __forceinline__ float sigm(float x) {
    return __fdividef(1.0f, 1.0f + __expf(-x));
}
__device__ __forceinline__ float tanh_s(float x) {
    float a = fabsf(x);
    float e = __expf(-2.0f * a);                 // e in (0,1], no overflow
    float r = __fdividef(1.0f - e, 1.0f + e);
    return copysignf(r, x);
}

// ---------------- K0: zero touched node state ----------------
__global__ void k_zero(const int* __restrict__ ei) {
    int node = ei[blockIdx.x];                   // blockIdx in [0, 2E)
    g_h[(size_t)node * HH + threadIdx.x] = 0.0f;
    g_c[(size_t)node * HH + threadIdx.x] = 0.0f;
}

// ---------------- K1a: time encodings (accurate cosf; args up to ~3e4) -----
__global__ void k_te(const float* __restrict__ etime,
                     const float* __restrict__ tw,
                     const float* __restrict__ tb) {
    int idx = blockIdx.x * blockDim.x + threadIdx.x;
    if (idx < EE * TE) {
        int e = idx >> 5, i = idx & 31;
        g_te[idx] = cosf(etime[e] * tw[i] + tb[i]);
    }
}

// ---------------- K1b: fold output linears: W2 = W_emb@W_cls --------------
__global__ void k_w2(const float* __restrict__ W_emb,
                     const float* __restrict__ b_emb,
                     const float* __restrict__ W_cls,
                     const float* __restrict__ b_cls) {
    int t = blockIdx.x * blockDim.x + threadIdx.x;
    if (t < KMSG * AA) {
        int i = t / AA, a = t % AA;
        float s = 0.0f;
        #pragma unroll 8
        for (int j = 0; j < HH; j++) s += W_emb[i * HH + j] * W_cls[j * AA + a];
        g_W2[t] = s;
    } else if (t < KMSG * AA + AA) {
        int a = t - KMSG * AA;
        float s = b_cls[a];
        #pragma unroll 8
        for (int j = 0; j < HH; j++) s += b_emb[j] * W_cls[j * AA + a];
        g_b2[a] = s;
    }
}

// ---------------- K2: sequential event scan (1 block, weights in regs) -----
__global__ __launch_bounds__(256, 1)
void k_scan(const int*   __restrict__ ei,
            const float* __restrict__ eattr,
            const float* __restrict__ W_msg,
            const float* __restrict__ b_msg,
            const float* __restrict__ W_ih,
            const float* __restrict__ W_hh,
            const float* __restrict__ b_lstm) {
    __shared__ __align__(16) float s_f0[KMSG];   // feat row0: [hd|hs|ea|te]
    __shared__ __align__(16) float s_f1[KMSG];   // feat row1: [hs|hd|ea|te]
    __shared__ __align__(16) float s_m0[HH];     // relu message row0
    __shared__ __align__(16) float s_m1[HH];     // relu message row1
    __shared__ __align__(16) float s_c[2][HH];   // old cell (cs, cd)
    __shared__ float2 s_part[4][HH];             // message partials {r0, r1}
    __shared__ float2 s_g[4 * HH];               // gates {r0, r1}
    __shared__ float  s_bmsg[HH];
    __shared__ float  s_blstm[4 * HH];

    const int t   = threadIdx.x;
    const int col = t & 63;
    const int seg = t >> 6;
    const int k0  = seg * 48;

    if (t < HH) s_bmsg[t] = b_msg[t];
    s_blstm[t] = b_lstm[t];

    // message weights: this thread holds W_msg[k0..k0+48)[col], k-paired
    ull wm[24];
    #pragma unroll
    for (int j = 0; j < 24; j++)
        wm[j] = f2u(W_msg[(k0 + 2*j) * HH + col], W_msg[(k0 + 2*j + 1) * HH + col]);

    // LSTM weights: this thread holds full columns t of W_ih and W_hh, k-paired
    ull wih[32], whh[32];
    #pragma unroll
    for (int i = 0; i < 32; i++) {
        wih[i] = f2u(W_ih[(2*i) * 256 + t], W_ih[(2*i + 1) * 256 + t]);
        whh[i] = f2u(W_hh[(2*i) * 256 + t], W_hh[(2*i + 1) * 256 + t]);
    }
    __syncthreads();

    for (int e = 0; e < EE; e++) {
        const int src = ei[e];
        const int dst = ei[EE + e];

        // ---- load node state + edge features into feat rows ----
        if (t < 64) {
            float v = g_h[(size_t)dst * HH + t];
            s_f0[t] = v;            // row0 leading = hd
            s_f1[64 + t] = v;       // row1 second  = hd
            s_c[1][t] = g_c[(size_t)dst * HH + t];
        } else if (t < 128) {
            int i = t - 64;
            float v = g_h[(size_t)src * HH + i];
            s_f0[64 + i] = v;       // row0 second  = hs
            s_f1[i] = v;            // row1 leading = hs
            s_c[0][i] = g_c[(size_t)src * HH + i];
        } else if (t < 160) {
            int i = t - 128;
            float v = eattr[e * EA + i];
            s_f0[128 + i] = v;
            s_f1[128 + i] = v;
        } else if (t < 192) {
            int i = t - 160;
            float v = g_te[e * TE + i];
            s_f0[160 + i] = v;
            s_f1[160 + i] = v;
        }
        __syncthreads();

        // ---- message GEMM: [2,192] @ [192,64]  (partials over 4 k-segments)
        {
            ull a0 = 0ull, a1 = 0ull;
            #pragma unroll
            for (int j = 0; j < 24; j++) {
                ull f0 = *(const ull*)(s_f0 + k0 + 2*j);
                ull f1 = *(const ull*)(s_f1 + k0 + 2*j);
                a0 = ffma2(f0, wm[j], a0);
                a1 = ffma2(f1, wm[j], a1);
            }
            float2 p0 = u2f(a0), p1 = u2f(a1);
            s_part[seg][col] = make_float2(p0.x + p0.y, p1.x + p1.y);
        }
        __syncthreads();

        if (t < HH) {
            float2 s = s_part[0][t];
            #pragma unroll
            for (int q = 1; q < 4; q++) { s.x += s_part[q][t].x; s.y += s_part[q][t].y; }
            float b = s_bmsg[t];
            s_m0[t] = fmaxf(s.x + b, 0.0f);
            s_m1[t] = fmaxf(s.y + b, 0.0f);
        }
        __syncthreads();

        // ---- LSTM gates: g = m@W_ih + h_old@W_hh + b  (one column per thread)
        {
            ull a0 = 0ull, a1 = 0ull;
            #pragma unroll
            for (int i = 0; i < 32; i++) {
                a0 = ffma2(*(const ull*)(s_m0 + 2*i),        wih[i], a0);
                a1 = ffma2(*(const ull*)(s_m1 + 2*i),        wih[i], a1);
                a0 = ffma2(*(const ull*)(s_f0 + 64 + 2*i),   whh[i], a0);  // hs (row0)
                a1 = ffma2(*(const ull*)(s_f1 + 64 + 2*i),   whh[i], a1);  // hd (row1)
            }
            float2 g0 = u2f(a0), g1 = u2f(a1);
            float b = s_blstm[t];
            s_g[t] = make_float2(g0.x + g0.y + b, g1.x + g1.y + b);
        }
        __syncthreads();

        // ---- elementwise LSTM + writeback ----
        if (t < 128) {
            int r = t >> 6, cc = t & 63;
            float2 vi = s_g[cc], vf = s_g[64 + cc], vg = s_g[128 + cc], vo = s_g[192 + cc];
            float gi = r ? vi.y : vi.x;
            float gf = r ? vf.y : vf.x;
            float gg = r ? vg.y : vg.x;
            float go = r ? vo.y : vo.x;
            float co = s_c[r][cc];
            float cn = sigm(gf) * co + sigm(gi) * tanh_s(gg);
            float hn = sigm(go) * tanh_s(cn);
            int node = r ? dst : src;
            // duplicate-index semantics: dst (row 1) wins, matching scatter order
            if (!(r == 0 && src == dst)) {
                g_h[(size_t)node * HH + cc] = hn;
                g_c[(size_t)node * HH + cc] = cn;
            }
        }
        __syncthreads();   // also makes global h/c writes visible block-wide
    }
}

// ---------------- K3: logits[e] = [h[dst] || x[dst]] @ W2 + b2 -------------
__global__ void k_logits(const int* __restrict__ ei,
                         const float* __restrict__ x,
                         float* __restrict__ out) {
    __shared__ float sz[KMSG];
    int e = blockIdx.x;
    int dst = ei[EE + e];
    int t = threadIdx.x;   // 64 threads
    sz[t]        = g_h[(size_t)dst * HH + t];
    sz[64 + t]   = x[(size_t)dst * DFEAT + t];
    sz[128 + t]  = x[(size_t)dst * DFEAT + 64 + t];
    __syncthreads();
    if (t < AA) {
        float s = g_b2[t];
        #pragma unroll 8
        for (int i = 0; i < KMSG; i++) s += sz[i] * g_W2[i * AA + t];
        out[e * AA + t] = s;
    }
}

// ---------------- launch ----------------
extern "C" void kernel_launch(void* const* d_in, const int* in_sizes, int n_in,
                              void* d_out, int out_size) {
    const float* x      = (const float*)d_in[0];
    const int*   ei     = (const int*)  d_in[1];
    const float* eattr  = (const float*)d_in[2];
    const float* etime  = (const float*)d_in[3];
    const float* tw     = (const float*)d_in[4];
    const float* tb     = (const float*)d_in[5];
    const float* Wmsg   = (const float*)d_in[6];
    const float* bmsg   = (const float*)d_in[7];
    const float* Wih    = (const float*)d_in[8];
    const float* Whh    = (const float*)d_in[9];
    const float* blstm  = (const float*)d_in[10];
    const float* Wemb   = (const float*)d_in[11];
    const float* bemb   = (const float*)d_in[12];
    const float* Wcls   = (const float*)d_in[13];
    const float* bcls   = (const float*)d_in[14];
    float* out = (float*)d_out;

    k_zero<<<2 * EE, HH>>>(ei);
    k_te<<<(EE * TE + 255) / 256, 256>>>(etime, tw, tb);
    k_w2<<<(KMSG * AA + AA + 255) / 256, 256>>>(Wemb, bemb, Wcls, bcls);
    k_scan<<<1, 256>>>(ei, eattr, Wmsg, bmsg, Wih, Whh, blstm);
    k_logits<<<EE, HH>>>(ei, x, out);
}

// round 4
// speedup vs baseline: 63.7738x; 63.7738x over previous
#include <cuda_runtime.h>
#include <cuda_bf16.h>

// ---------------- problem constants ----------------
#define NN     200000   // nodes
#define DFEAT  128
#define EE     8192     // events
#define HH     64
#define TE     32
#define EA     32
#define AA     50
#define KMSG   (2*HH + EA + TE)   // 192
#define GRID_SCAN 148             // one block per SM (B200) -> all co-resident

// ---------------- scratch (static device globals; allocation is forbidden) --
__device__ float g_h[(size_t)NN * HH];     // node memory
__device__ float g_c[(size_t)NN * HH];     // LSTM cell
__device__ float g_te[EE * TE];            // time encodings
__device__ float g_W2[KMSG * AA];          // fused W_emb @ W_cls
__device__ float g_b2[AA];                 // fused bias

__device__ int                g_done[EE];      // event completion flags
__device__ int                g_ncount[NN];    // endpoint occurrence counts
__device__ int                g_pred[2 * EE];  // per-endpoint predecessor position (-1 = none)
__device__ unsigned long long g_list[2 * EE];  // (node<<32)|pos for multi-occurrence endpoints
__device__ int                g_npos;          // compacted count

// ---------------- helpers ----------------
using ull = unsigned long long;

__device__ __forceinline__ ull ffma2(ull a, ull b, ull c) {
    ull d;
    asm("fma.rn.f32x2 %0, %1, %2, %3;" : "=l"(d) : "l"(a), "l"(b), "l"(c));
    return d;
}
__device__ __forceinline__ ull f2u(float x, float y) {
    ull v;
    asm("mov.b64 %0, {%1, %2};" : "=l"(v) : "f"(x), "f"(y));
    return v;
}
__device__ __forceinline__ float2 u2f(ull v) {
    float2 r;
    asm("mov.b64 {%0, %1}, %2;" : "=f"(r.x), "=f"(r.y) : "l"(v));
    return r;
}
__device__ __forceinline__ float sigm(float x) {
    return __fdividef(1.0f, 1.0f + __expf(-x));
}
__device__ __forceinline__ float tanh_s(float x) {
    float a = fabsf(x);
    float e = __expf(-2.0f * a);
    float r = __fdividef(1.0f - e, 1.0f + e);
    return copysignf(r, x);
}
__device__ __forceinline__ void wait_done(int e) {
    unsigned v;
    do {
        asm volatile("ld.global.acquire.gpu.b32 %0, [%1];" : "=r"(v) : "l"(g_done + e) : "memory");
    } while (v == 0u);
}
__device__ __forceinline__ void signal_done(int e) {
    asm volatile("st.global.release.gpu.b32 [%0], %1;" :: "l"(g_done + e), "r"(1) : "memory");
}

// ---------------- K0a: reset scratch ----------------
__global__ void k_reset() {
    int i = blockIdx.x * blockDim.x + threadIdx.x;
    if (i < NN) g_ncount[i] = 0;
    if (i < EE) g_done[i] = 0;
    if (i < 2 * EE) g_pred[i] = -1;
    if (i == 0) g_npos = 0;
}

// ---------------- K0b: zero touched node state ----------------
__global__ void k_zero(const int* __restrict__ ei) {
    int node = ei[blockIdx.x];                   // blockIdx in [0, 2E)
    g_h[(size_t)node * HH + threadIdx.x] = 0.0f;
    g_c[(size_t)node * HH + threadIdx.x] = 0.0f;
}

// ---------------- K1a: time encodings (accurate cosf) ----------------------
__global__ void k_te(const float* __restrict__ etime,
                     const float* __restrict__ tw,
                     const float* __restrict__ tb) {
    int idx = blockIdx.x * blockDim.x + threadIdx.x;
    if (idx < EE * TE) {
        int e = idx >> 5, i = idx & 31;
        g_te[idx] = cosf(etime[e] * tw[i] + tb[i]);
    }
}

// ---------------- K1b: fold output linears: W2 = W_emb@W_cls --------------
__global__ void k_w2(const float* __restrict__ W_emb,
                     const float* __restrict__ b_emb,
                     const float* __restrict__ W_cls,
                     const float* __restrict__ b_cls) {
    int t = blockIdx.x * blockDim.x + threadIdx.x;
    if (t < KMSG * AA) {
        int i = t / AA, a = t % AA;
        float s = 0.0f;
        #pragma unroll 8
        for (int j = 0; j < HH; j++) s += W_emb[i * HH + j] * W_cls[j * AA + a];
        g_W2[t] = s;
    } else if (t < KMSG * AA + AA) {
        int a = t - KMSG * AA;
        float s = b_cls[a];
        #pragma unroll 8
        for (int j = 0; j < HH; j++) s += b_emb[j] * W_cls[j * AA + a];
        g_b2[a] = s;
    }
}

// ---------------- P1: count endpoint occurrences (self-loops deduped) ------
__global__ void k_count(const int* __restrict__ ei) {
    int i = blockIdx.x * blockDim.x + threadIdx.x;
    if (i >= 2 * EE) return;
    int e = i >> 1;
    int src = ei[e], dst = ei[EE + e];
    if ((i & 1) && src == dst) return;           // dedupe self-loop endpoint
    atomicAdd(&g_ncount[(i & 1) ? dst : src], 1);
}

// ---------------- P2: compact multi-occurrence endpoints -------------------
__global__ void k_compact(const int* __restrict__ ei) {
    int i = blockIdx.x * blockDim.x + threadIdx.x;
    if (i >= 2 * EE) return;
    int e = i >> 1;
    int src = ei[e], dst = ei[EE + e];
    if ((i & 1) && src == dst) return;
    int v = (i & 1) ? dst : src;
    if (g_ncount[v] >= 2) {
        int pos = atomicAdd(&g_npos, 1);
        g_list[pos] = ((ull)(unsigned)v << 32) | (unsigned)i;
    }
}

// ---------------- P3: bitonic sort -> predecessor extraction ---------------
// One block. Sort (node,pos) keys ascending; equal-node neighbors give pred.
// Deterministic regardless of P2's atomic compaction order (pos is in the key).
__global__ void k_sort_pred() {
    extern __shared__ ull skey[];
    const int t = threadIdx.x, T = blockDim.x;
    const int n = g_npos;
    int m = 2;
    while (m < n) m <<= 1;                       // n <= 16384 -> m <= 16384

    for (int i = t; i < m; i += T)
        skey[i] = (i < n) ? g_list[i] : ~0ull;
    __syncthreads();

    for (int k = 2; k <= m; k <<= 1) {
        for (int j = k >> 1; j > 0; j >>= 1) {
            for (int i = t; i < m; i += T) {
                int ixj = i ^ j;
                if (ixj > i) {
                    ull a = skey[i], b = skey[ixj];
                    bool up = ((i & k) == 0);
                    if ((a > b) == up) { skey[i] = b; skey[ixj] = a; }
                }
            }
            __syncthreads();
        }
    }
    for (int i = t + 1; i < n; i += T) {
        ull a = skey[i - 1], b = skey[i];
        if ((a >> 32) == (b >> 32))
            g_pred[(unsigned)b] = (int)(unsigned)a;   // low 32 bits = position
    }
}

// ---------------- K2: parallel dependency-driven event scan ----------------
// 148 persistent blocks (all co-resident). Block b owns events b, b+148, ...
// Exact sequential semantics enforced by spinning on predecessor done-flags.
__global__ __launch_bounds__(256, 1)
void k_scan(const int*   __restrict__ ei,
            const float* __restrict__ eattr,
            const float* __restrict__ W_msg,
            const float* __restrict__ b_msg,
            const float* __restrict__ W_ih,
            const float* __restrict__ W_hh,
            const float* __restrict__ b_lstm) {
    __shared__ __align__(16) float s_f0[KMSG];   // feat row0: [hd|hs|ea|te]
    __shared__ __align__(16) float s_f1[KMSG];   // feat row1: [hs|hd|ea|te]
    __shared__ __align__(16) float s_m0[HH];     // relu message row0
    __shared__ __align__(16) float s_m1[HH];     // relu message row1
    __shared__ __align__(16) float s_c[2][HH];   // old cell (cs, cd)
    __shared__ float2 s_part[4][HH];             // message partials {r0, r1}
    __shared__ float2 s_g[4 * HH];               // gates {r0, r1}
    __shared__ float  s_bmsg[HH];
    __shared__ float  s_blstm[4 * HH];

    const int t   = threadIdx.x;
    const int col = t & 63;
    const int seg = t >> 6;
    const int k0  = seg * 48;

    if (t < HH) s_bmsg[t] = b_msg[t];
    s_blstm[t] = b_lstm[t];

    // message weights: this thread holds W_msg[k0..k0+48)[col], k-paired
    ull wm[24];
    #pragma unroll
    for (int j = 0; j < 24; j++)
        wm[j] = f2u(W_msg[(k0 + 2*j) * HH + col], W_msg[(k0 + 2*j + 1) * HH + col]);

    // LSTM weights: full columns t of W_ih and W_hh, k-paired
    ull wih[32], whh[32];
    #pragma unroll
    for (int i = 0; i < 32; i++) {
        wih[i] = f2u(W_ih[(2*i) * 256 + t], W_ih[(2*i + 1) * 256 + t]);
        whh[i] = f2u(W_hh[(2*i) * 256 + t], W_hh[(2*i + 1) * 256 + t]);
    }
    __syncthreads();

    for (int e = blockIdx.x; e < EE; e += GRID_SCAN) {
        const int src = ei[e];
        const int dst = ei[EE + e];

        // ---- wait for exact predecessors (two warps spin in parallel) ----
        if (t == 0) {
            int p = g_pred[2 * e];
            if (p >= 0) wait_done(p >> 1);
        } else if (t == 32) {
            int p = g_pred[2 * e + 1];
            if (p >= 0) wait_done(p >> 1);
        }
        __syncthreads();

        // ---- load node state (L2-coherent) + edge features ----
        if (t < 64) {
            float v = __ldcg(&g_h[(size_t)dst * HH + t]);
            s_f0[t] = v;            // row0 leading = hd
            s_f1[64 + t] = v;       // row1 second  = hd
            s_c[1][t] = __ldcg(&g_c[(size_t)dst * HH + t]);
        } else if (t < 128) {
            int i = t - 64;
            float v = __ldcg(&g_h[(size_t)src * HH + i]);
            s_f0[64 + i] = v;       // row0 second  = hs
            s_f1[i] = v;            // row1 leading = hs
            s_c[0][i] = __ldcg(&g_c[(size_t)src * HH + i]);
        } else if (t < 160) {
            int i = t - 128;
            float v = eattr[e * EA + i];
            s_f0[128 + i] = v;
            s_f1[128 + i] = v;
        } else if (t < 192) {
            int i = t - 160;
            float v = g_te[e * TE + i];
            s_f0[160 + i] = v;
            s_f1[160 + i] = v;
        }
        __syncthreads();

        // ---- message GEMM: [2,192] @ [192,64] (4 k-segment partials) ----
        {
            ull a0 = 0ull, a1 = 0ull;
            #pragma unroll
            for (int j = 0; j < 24; j++) {
                ull f0 = *(const ull*)(s_f0 + k0 + 2*j);
                ull f1 = *(const ull*)(s_f1 + k0 + 2*j);
                a0 = ffma2(f0, wm[j], a0);
                a1 = ffma2(f1, wm[j], a1);
            }
            float2 p0 = u2f(a0), p1 = u2f(a1);
            s_part[seg][col] = make_float2(p0.x + p0.y, p1.x + p1.y);
        }
        __syncthreads();

        if (t < HH) {
            float2 s = s_part[0][t];
            #pragma unroll
            for (int q = 1; q < 4; q++) { s.x += s_part[q][t].x; s.y += s_part[q][t].y; }
            float b = s_bmsg[t];
            s_m0[t] = fmaxf(s.x + b, 0.0f);
            s_m1[t] = fmaxf(s.y + b, 0.0f);
        }
        __syncthreads();

        // ---- LSTM gates: g = m@W_ih + h_old@W_hh + b ----
        {
            ull a0 = 0ull, a1 = 0ull;
            #pragma unroll
            for (int i = 0; i < 32; i++) {
                a0 = ffma2(*(const ull*)(s_m0 + 2*i),      wih[i], a0);
                a1 = ffma2(*(const ull*)(s_m1 + 2*i),      wih[i], a1);
                a0 = ffma2(*(const ull*)(s_f0 + 64 + 2*i), whh[i], a0);  // hs (row0)
                a1 = ffma2(*(const ull*)(s_f1 + 64 + 2*i), whh[i], a1);  // hd (row1)
            }
            float2 g0 = u2f(a0), g1 = u2f(a1);
            float b = s_blstm[t];
            s_g[t] = make_float2(g0.x + g0.y + b, g1.x + g1.y + b);
        }
        __syncthreads();

        // ---- elementwise LSTM + writeback ----
        if (t < 128) {
            int r = t >> 6, cc = t & 63;
            float2 vi = s_g[cc], vf = s_g[64 + cc], vg = s_g[128 + cc], vo = s_g[192 + cc];
            float gi = r ? vi.y : vi.x;
            float gf = r ? vf.y : vf.x;
            float gg = r ? vg.y : vg.x;
            float go = r ? vo.y : vo.x;
            float co = s_c[r][cc];
            float cn = sigm(gf) * co + sigm(gi) * tanh_s(gg);
            float hn = sigm(go) * tanh_s(cn);
            int node = r ? dst : src;
            // duplicate-index semantics: dst (row 1) wins, matching scatter order
            if (!(r == 0 && src == dst)) {
                __stcg(&g_h[(size_t)node * HH + cc], hn);
                __stcg(&g_c[(size_t)node * HH + cc], cn);
            }
        }
        __syncthreads();                 // writes done block-wide before release

        if (t == 0) signal_done(e);      // release: publishes h/c to consumers
    }
}

// ---------------- K3: logits[e] = [h[dst] || x[dst]] @ W2 + b2 -------------
__global__ void k_logits(const int* __restrict__ ei,
                         const float* __restrict__ x,
                         float* __restrict__ out) {
    __shared__ float sz[KMSG];
    int e = blockIdx.x;
    int dst = ei[EE + e];
    int t = threadIdx.x;   // 64 threads
    sz[t]        = g_h[(size_t)dst * HH + t];
    sz[64 + t]   = x[(size_t)dst * DFEAT + t];
    sz[128 + t]  = x[(size_t)dst * DFEAT + 64 + t];
    __syncthreads();
    if (t < AA) {
        float s = g_b2[t];
        #pragma unroll 8
        for (int i = 0; i < KMSG; i++) s += sz[i] * g_W2[i * AA + t];
        out[e * AA + t] = s;
    }
}

// ---------------- launch ----------------
extern "C" void kernel_launch(void* const* d_in, const int* in_sizes, int n_in,
                              void* d_out, int out_size) {
    const float* x      = (const float*)d_in[0];
    const int*   ei     = (const int*)  d_in[1];
    const float* eattr  = (const float*)d_in[2];
    const float* etime  = (const float*)d_in[3];
    const float* tw     = (const float*)d_in[4];
    const float* tb     = (const float*)d_in[5];
    const float* Wmsg   = (const float*)d_in[6];
    const float* bmsg   = (const float*)d_in[7];
    const float* Wih    = (const float*)d_in[8];
    const float* Whh    = (const float*)d_in[9];
    const float* blstm  = (const float*)d_in[10];
    const float* Wemb   = (const float*)d_in[11];
    const float* bemb   = (const float*)d_in[12];
    const float* Wcls   = (const float*)d_in[13];
    const float* bcls   = (const float*)d_in[14];
    float* out = (float*)d_out;

    static bool attr_set = false;
    if (!attr_set) {
        cudaFuncSetAttribute(k_sort_pred,
                             cudaFuncAttributeMaxDynamicSharedMemorySize,
                             2 * EE * (int)sizeof(unsigned long long));
        attr_set = true;
    }

    k_reset  <<<(NN + 255) / 256, 256>>>();
    k_zero   <<<2 * EE, HH>>>(ei);
    k_te     <<<(EE * TE + 255) / 256, 256>>>(etime, tw, tb);
    k_w2     <<<(KMSG * AA + AA + 255) / 256, 256>>>(Wemb, bemb, Wcls, bcls);
    k_count  <<<(2 * EE + 255) / 256, 256>>>(ei);
    k_compact<<<(2 * EE + 255) / 256, 256>>>(ei);
    k_sort_pred<<<1, 1024, 2 * EE * (int)sizeof(unsigned long long)>>>();
    k_scan   <<<GRID_SCAN, 256>>>(ei, eattr, Wmsg, bmsg, Wih, Whh, blstm);
    k_logits <<<EE, HH>>>(ei, x, out);
}

// round 7
// speedup vs baseline: 76.2426x; 1.1955x over previous
#include <cuda_runtime.h>
#include <cuda_bf16.h>

// ---------------- problem constants ----------------
#define NN     200000   // nodes
#define DFEAT  128
#define EE     8192     // events
#define HH     64
#define TE     32
#define EA     32
#define AA     50
#define KMSG   (2*HH + EA + TE)   // 192
#define GRID_SCAN 148             // one block per SM -> all co-resident

// ---------------- scratch (static device globals; allocation is forbidden) --
__device__ float g_h[(size_t)NN * HH];     // node memory (only written slots are ever read)
__device__ float g_c[(size_t)NN * HH];     // LSTM cell
__device__ float g_te[EE * TE];            // time encodings
__device__ float g_W2[KMSG * AA];          // fused W_emb @ W_cls
__device__ float g_b2[AA];                 // fused bias

__device__ int                g_done[EE];      // event completion flags
__device__ int                g_ncount[NN];    // endpoint occurrence counts
__device__ int                g_pred[2 * EE];  // per-endpoint predecessor position (-1 = none)
__device__ unsigned long long g_list[2 * EE];  // (node<<32)|pos for multi-occurrence endpoints
__device__ int                g_npos;          // compacted count

// ---------------- helpers ----------------
using ull = unsigned long long;

__device__ __forceinline__ ull ffma2(ull a, ull b, ull c) {
    ull d;
    asm("fma.rn.f32x2 %0, %1, %2, %3;" : "=l"(d) : "l"(a), "l"(b), "l"(c));
    return d;
}
__device__ __forceinline__ ull f2u(float x, float y) {
    ull v;
    asm("mov.b64 %0, {%1, %2};" : "=l"(v) : "f"(x), "f"(y));
    return v;
}
__device__ __forceinline__ float2 u2f(ull v) {
    float2 r;
    asm("mov.b64 {%0, %1}, %2;" : "=f"(r.x), "=f"(r.y) : "l"(v));
    return r;
}
__device__ __forceinline__ float sigm(float x) {
    return __fdividef(1.0f, 1.0f + __expf(-x));
}
__device__ __forceinline__ float tanh_s(float x) {
    float a = fabsf(x);
    float e = __expf(-2.0f * a);
    float r = __fdividef(1.0f - e, 1.0f + e);
    return copysignf(r, x);
}
__device__ __forceinline__ void wait_done(int e) {
    unsigned v;
    do {
        asm volatile("ld.global.acquire.gpu.b32 %0, [%1];" : "=r"(v) : "l"(g_done + e) : "memory");
    } while (v == 0u);
}
__device__ __forceinline__ void signal_done(int e) {
    asm volatile("st.global.release.gpu.b32 [%0], %1;" :: "l"(g_done + e), "r"(1) : "memory");
}

// ---------------- K0: reset scratch ----------------
__global__ void k_reset() {
    int i = blockIdx.x * blockDim.x + threadIdx.x;
    if (i < NN) g_ncount[i] = 0;
    if (i < EE) g_done[i] = 0;
    if (i < 2 * EE) g_pred[i] = -1;
    if (i == 0) g_npos = 0;
}

// ---------------- K1a: time encodings (accurate cosf) ----------------------
__global__ void k_te(const float* __restrict__ etime,
                     const float* __restrict__ tw,
                     const float* __restrict__ tb) {
    int idx = blockIdx.x * blockDim.x + threadIdx.x;
    if (idx < EE * TE) {
        int e = idx >> 5, i = idx & 31;
        g_te[idx] = cosf(etime[e] * tw[i] + tb[i]);
    }
}

// ---------------- K1b: fold output linears: W2 = W_emb@W_cls --------------
// grid = KMSG+1 blocks of 64 threads. Block i holds W_emb row i in smem;
// threads 0..49 read W_cls coalesced (consecutive a for fixed j).
__global__ void k_w2(const float* __restrict__ W_emb,
                     const float* __restrict__ b_emb,
                     const float* __restrict__ W_cls,
                     const float* __restrict__ b_cls) {
    __shared__ float srow[HH];
    const int blk = blockIdx.x, t = threadIdx.x;
    if (blk < KMSG) {
        srow[t] = W_emb[blk * HH + t];
        __syncthreads();
        if (t < AA) {
            float s = 0.0f;
            #pragma unroll 16
            for (int j = 0; j < HH; j++) s += srow[j] * W_cls[j * AA + t];
            g_W2[blk * AA + t] = s;
        }
    } else {
        srow[t] = b_emb[t];
        __syncthreads();
        if (t < AA) {
            float s = b_cls[t];
            #pragma unroll 16
            for (int j = 0; j < HH; j++) s += srow[j] * W_cls[j * AA + t];
            g_b2[t] = s;
        }
    }
}

// ---------------- P1: count endpoint occurrences (self-loops deduped) ------
__global__ void k_count(const int* __restrict__ ei) {
    int i = blockIdx.x * blockDim.x + threadIdx.x;
    if (i >= 2 * EE) return;
    int e = i >> 1;
    int src = ei[e], dst = ei[EE + e];
    if ((i & 1) && src == dst) return;           // dedupe self-loop endpoint
    atomicAdd(&g_ncount[(i & 1) ? dst : src], 1);
}

// ---------------- P2: compact multi-occurrence endpoints -------------------
__global__ void k_compact(const int* __restrict__ ei) {
    int i = blockIdx.x * blockDim.x + threadIdx.x;
    if (i >= 2 * EE) return;
    int e = i >> 1;
    int src = ei[e], dst = ei[EE + e];
    if ((i & 1) && src == dst) return;
    int v = (i & 1) ? dst : src;
    if (g_ncount[v] >= 2) {
        int pos = atomicAdd(&g_npos, 1);
        g_list[pos] = ((ull)(unsigned)v << 32) | (unsigned)i;
    }
}

// ---------------- P3: bitonic sort -> predecessor extraction ---------------
// One block. Sort (node,pos) keys ascending; equal-node neighbors give pred.
// Deterministic regardless of P2's atomic compaction order (pos is in the key).
__global__ void k_sort_pred() {
    extern __shared__ ull skey[];
    const int t = threadIdx.x, T = blockDim.x;
    const int n = g_npos;
    int m = 2;
    while (m < n) m <<= 1;                       // n <= 16384

    for (int i = t; i < m; i += T)
        skey[i] = (i < n) ? g_list[i] : ~0ull;
    __syncthreads();

    for (int k = 2; k <= m; k <<= 1) {
        for (int j = k >> 1; j > 0; j >>= 1) {
            for (int i = t; i < m; i += T) {
                int ixj = i ^ j;
                if (ixj > i) {
                    ull a = skey[i], b = skey[ixj];
                    bool up = ((i & k) == 0);
                    if ((a > b) == up) { skey[i] = b; skey[ixj] = a; }
                }
            }
            __syncthreads();
        }
    }
    for (int i = t + 1; i < n; i += T) {
        ull a = skey[i - 1], b = skey[i];
        if ((a >> 32) == (b >> 32))
            g_pred[(unsigned)b] = (int)(unsigned)a;   // low 32 bits = position
    }
}

// ---------------- K2: parallel dependency-driven event scan ----------------
// 148 persistent blocks. Block b owns events b, b+148, ...  Exact sequential
// semantics via per-endpoint predecessor flags. Zero-state invariant:
// pred == -1  =>  that node's (h,c) is exactly 0, so no global load needed.
__global__ __launch_bounds__(256, 1)
void k_scan(const int*   __restrict__ ei,
            const float* __restrict__ eattr,
            const float* __restrict__ W_msg,
            const float* __restrict__ b_msg,
            const float* __restrict__ W_ih,
            const float* __restrict__ W_hh,
            const float* __restrict__ b_lstm) {
    __shared__ __align__(16) float s_f0[KMSG];   // feat row0: [hd|hs|ea|te]
    __shared__ __align__(16) float s_f1[KMSG];   // feat row1: [hs|hd|ea|te]
    __shared__ __align__(16) float s_m0[HH];     // relu message row0
    __shared__ __align__(16) float s_m1[HH];     // relu message row1
    __shared__ __align__(16) float s_c[2][HH];   // old cell (cs, cd)
    __shared__ float2 s_part[4][HH];             // message partials {r0, r1}
    __shared__ float2 s_g[4 * HH];               // gates {r0, r1}
    __shared__ float  s_bmsg[HH];
    __shared__ float  s_blstm[4 * HH];

    const int t   = threadIdx.x;
    const int col = t & 63;
    const int seg = t >> 6;
    const int k0  = seg * 48;

    if (t < HH) s_bmsg[t] = b_msg[t];
    s_blstm[t] = b_lstm[t];

    // message weights: this thread holds W_msg[k0..k0+48)[col], k-paired
    ull wm[24];
    #pragma unroll
    for (int j = 0; j < 24; j++)
        wm[j] = f2u(W_msg[(k0 + 2*j) * HH + col], W_msg[(k0 + 2*j + 1) * HH + col]);

    // LSTM weights: full columns t of W_ih and W_hh, k-paired
    ull wih[32], whh[32];
    #pragma unroll
    for (int i = 0; i < 32; i++) {
        wih[i] = f2u(W_ih[(2*i) * 256 + t], W_ih[(2*i + 1) * 256 + t]);
        whh[i] = f2u(W_hh[(2*i) * 256 + t], W_hh[(2*i + 1) * 256 + t]);
    }
    __syncthreads();

    for (int e = blockIdx.x; e < EE; e += GRID_SCAN) {
        const int src = ei[e];
        const int dst = ei[EE + e];
        const int ps  = g_pred[2 * e];
        int       pd  = g_pred[2 * e + 1];
        if (src == dst) pd = ps;   // self-loop: dst endpoint was deduped

        // ---- per-thread wait + state load (zeros when no predecessor) ----
        if (t < 64) {
            float vh = 0.0f, vc = 0.0f;
            if (pd >= 0) {
                wait_done(pd >> 1);
                vh = __ldcg(&g_h[(size_t)dst * HH + t]);
                vc = __ldcg(&g_c[(size_t)dst * HH + t]);
            }
            s_f0[t] = vh;           // row0 leading = hd
            s_f1[64 + t] = vh;      // row1 second  = hd
            s_c[1][t] = vc;
        } else if (t < 128) {
            int i = t - 64;
            float vh = 0.0f, vc = 0.0f;
            if (ps >= 0) {
                wait_done(ps >> 1);
                vh = __ldcg(&g_h[(size_t)src * HH + i]);
                vc = __ldcg(&g_c[(size_t)src * HH + i]);
            }
            s_f0[64 + i] = vh;      // row0 second  = hs
            s_f1[i] = vh;           // row1 leading = hs
            s_c[0][i] = vc;
        } else if (t < 160) {
            int i = t - 128;
            float v = eattr[e * EA + i];
            s_f0[128 + i] = v;
            s_f1[128 + i] = v;
        } else if (t < 192) {
            int i = t - 160;
            float v = g_te[e * TE + i];
            s_f0[160 + i] = v;
            s_f1[160 + i] = v;
        }
        __syncthreads();

        // ---- message GEMM: [2,192] @ [192,64] (4 k-segment partials) ----
        {
            ull a0 = 0ull, a1 = 0ull;
            #pragma unroll
            for (int j = 0; j < 24; j++) {
                ull f0 = *(const ull*)(s_f0 + k0 + 2*j);
                ull f1 = *(const ull*)(s_f1 + k0 + 2*j);
                a0 = ffma2(f0, wm[j], a0);
                a1 = ffma2(f1, wm[j], a1);
            }
            float2 p0 = u2f(a0), p1 = u2f(a1);
            s_part[seg][col] = make_float2(p0.x + p0.y, p1.x + p1.y);
        }
        __syncthreads();

        if (t < HH) {
            float2 s = s_part[0][t];
            #pragma unroll
            for (int q = 1; q < 4; q++) { s.x += s_part[q][t].x; s.y += s_part[q][t].y; }
            float b = s_bmsg[t];
            s_m0[t] = fmaxf(s.x + b, 0.0f);
            s_m1[t] = fmaxf(s.y + b, 0.0f);
        }
        __syncthreads();

        // ---- LSTM gates: g = m@W_ih + h_old@W_hh + b (split accumulators) --
        {
            ull a0 = 0ull, b0 = 0ull, a1 = 0ull, b1 = 0ull;
            #pragma unroll
            for (int i = 0; i < 32; i++) {
                a0 = ffma2(*(const ull*)(s_m0 + 2*i),      wih[i], a0);
                a1 = ffma2(*(const ull*)(s_m1 + 2*i),      wih[i], a1);
                b0 = ffma2(*(const ull*)(s_f0 + 64 + 2*i), whh[i], b0);  // hs (row0)
                b1 = ffma2(*(const ull*)(s_f1 + 64 + 2*i), whh[i], b1);  // hd (row1)
            }
            float2 g0 = u2f(a0), h0 = u2f(b0), g1 = u2f(a1), h1 = u2f(b1);
            float b = s_blstm[t];
            s_g[t] = make_float2(g0.x + g0.y + h0.x + h0.y + b,
                                 g1.x + g1.y + h1.x + h1.y + b);
        }
        __syncthreads();

        // ---- elementwise LSTM + writeback ----
        if (t < 128) {
            int r = t >> 6, cc = t & 63;
            float2 vi = s_g[cc], vf = s_g[64 + cc], vg = s_g[128 + cc], vo = s_g[192 + cc];
            float gi = r ? vi.y : vi.x;
            float gf = r ? vf.y : vf.x;
            float gg = r ? vg.y : vg.x;
            float go = r ? vo.y : vo.x;
            float co = s_c[r][cc];
            float cn = sigm(gf) * co + sigm(gi) * tanh_s(gg);
            float hn = sigm(go) * tanh_s(cn);
            int node = r ? dst : src;
            // duplicate-index semantics: dst (row 1) wins, matching scatter order
            if (!(r == 0 && src == dst)) {
                __stcg(&g_h[(size_t)node * HH + cc], hn);
                __stcg(&g_c[(size_t)node * HH + cc], cn);
            }
        }
        __syncthreads();                 // writes done block-wide before release

        if (t == 0) signal_done(e);      // release: publishes h/c to consumers
    }
}

// ---------------- K3: logits[e] = [h[dst] || x[dst]] @ W2 + b2 -------------
__global__ void k_logits(const int* __restrict__ ei,
                         const float* __restrict__ x,
                         float* __restrict__ out) {
    __shared__ float sz[KMSG];
    int e = blockIdx.x;
    int dst = ei[EE + e];
    int t = threadIdx.x;   // 64 threads
    sz[t]        = g_h[(size_t)dst * HH + t];   // always written by scan (dst of event e)
    sz[64 + t]   = x[(size_t)dst * DFEAT + t];
    sz[128 + t]  = x[(size_t)dst * DFEAT + 64 + t];
    __syncthreads();
    if (t < AA) {
        float s = g_b2[t];
        #pragma unroll 8
        for (int i = 0; i < KMSG; i++) s += sz[i] * g_W2[i * AA + t];
        out[e * AA + t] = s;
    }
}

// ---------------- launch ----------------
extern "C" void kernel_launch(void* const* d_in, const int* in_sizes, int n_in,
                              void* d_out, int out_size) {
    const float* x      = (const float*)d_in[0];
    const int*   ei     = (const int*)  d_in[1];
    const float* eattr  = (const float*)d_in[2];
    const float* etime  = (const float*)d_in[3];
    const float* tw     = (const float*)d_in[4];
    const float* tb     = (const float*)d_in[5];
    const float* Wmsg   = (const float*)d_in[6];
    const float* bmsg   = (const float*)d_in[7];
    const float* Wih    = (const float*)d_in[8];
    const float* Whh    = (const float*)d_in[9];
    const float* blstm  = (const float*)d_in[10];
    const float* Wemb   = (const float*)d_in[11];
    const float* bemb   = (const float*)d_in[12];
    const float* Wcls   = (const float*)d_in[13];
    const float* bcls   = (const float*)d_in[14];
    float* out = (float*)d_out;

    // idempotent, host-side only (not a stream op) -> safe under capture,
    // no static guard (harness forbids call-count-dependent behavior)
    cudaFuncSetAttribute(k_sort_pred,
                         cudaFuncAttributeMaxDynamicSharedMemorySize,
                         2 * EE * (int)sizeof(unsigned long long));

    k_reset  <<<(NN + 255) / 256, 256>>>();
    k_te     <<<(EE * TE + 255) / 256, 256>>>(etime, tw, tb);
    k_w2     <<<KMSG + 1, HH>>>(Wemb, bemb, Wcls, bcls);
    k_count  <<<(2 * EE + 255) / 256, 256>>>(ei);
    k_compact<<<(2 * EE + 255) / 256, 256>>>(ei);
    k_sort_pred<<<1, 1024, 2 * EE * (int)sizeof(unsigned long long)>>>();
    k_scan   <<<GRID_SCAN, 256>>>(ei, eattr, Wmsg, bmsg, Wih, Whh, blstm);
    k_logits <<<EE, HH>>>(ei, x, out);
}